// round 5
// baseline (speedup 1.0000x reference)
#include <cuda_runtime.h>
#include <cstdint>

#define BATCH 64
#define TLEN  512
#define D     1024

// ---------------- scratch (device globals: no allocations allowed) ----------------
__device__ float g_ext[(size_t)TLEN * BATCH * D];   // 128 MB, layout [t][b][o]
__device__ float g_stateA[BATCH * D];
__device__ float g_stateB[BATCH * D];
__device__ unsigned g_bars[4 * 32];                  // per-m-group barrier counters

// ---------------- packed f32x2 helpers (sm_103a FFMA2 path) ----------------
static __device__ __forceinline__ unsigned long long pack_dup(float w) {
    unsigned long long r;
    asm("mov.b64 %0, {%1, %1};" : "=l"(r) : "f"(w));
    return r;
}
static __device__ __forceinline__ void fma2(unsigned long long& d,
                                            unsigned long long a,
                                            unsigned long long b) {
    asm("fma.rn.f32x2 %0, %1, %2, %0;" : "+l"(d) : "l"(a), "l"(b));
}
static __device__ __forceinline__ void unpack2(unsigned long long v, float& lo, float& hi) {
    asm("mov.b64 {%0, %1}, %2;" : "=f"(lo), "=f"(hi) : "l"(v));
}

// ---------------- trivial zero kernels ----------------
__global__ void zero4_kernel(float4* __restrict__ p, int n4) {
    int i = blockIdx.x * blockDim.x + threadIdx.x;
    if (i < n4) p[i] = make_float4(0.f, 0.f, 0.f, 0.f);
}
__global__ void zero_state_kernel() {
    int i = blockIdx.x * blockDim.x + threadIdx.x;
    if (i < BATCH * D) g_stateA[i] = 0.f;
    if (i < 4 * 32) g_bars[i] = 0u;
}

// ---------------- Phase A: ext[t][b][o] = sum_k x[b][t][k] * W_in[o][k] ----------------
// M=32768 (m = b*512+t), N=1024, K=1024. BM=128, BN=64, BK=32, 256 threads,
// 8m x 4n per thread, double-buffered smem ping-pong.
#define BM 128
#define BN 64
#define BK 32
#define PADA 134
#define PADB 68
#define ASTRIDE (BK * PADA)
#define BSTRIDE (BK * PADB)
#define EXT_SMEM ((2 * ASTRIDE + 2 * BSTRIDE) * 4)   // 51712 B

__global__ __launch_bounds__(256) void ext_gemm_kernel(const float* __restrict__ X,
                                                       const float* __restrict__ Win) {
    extern __shared__ float esm[];
    float* As = esm;
    float* Bs = esm + 2 * ASTRIDE;

    const int tid = threadIdx.x;
    const int Mb = blockIdx.y * BM;
    const int Nb = blockIdx.x * BN;
    const int ty = tid >> 4, tx = tid & 15;
    const int m0 = ty * 8, n0 = tx * 4;

    unsigned long long acc[4][4];
#pragma unroll
    for (int i = 0; i < 4; ++i)
#pragma unroll
        for (int j = 0; j < 4; ++j) acc[i][j] = 0ULL;

    const int ar = tid >> 3, ac = tid & 7;
    const int br = tid >> 2, bc = tid & 3;

    float4 ra[4], rb[2];
#pragma unroll
    for (int g = 0; g < 4; ++g)
        ra[g] = *(const float4*)&X[(size_t)(Mb + ar + g * 32) * D + ac * 4];
#pragma unroll
    for (int g = 0; g < 2; ++g)
        rb[g] = *(const float4*)&Win[(size_t)(Nb + br) * D + (bc + g * 4) * 4];
    {
#pragma unroll
        for (int g = 0; g < 4; ++g) {
            const int m = ar + g * 32;
            As[(ac * 4 + 0) * PADA + m] = ra[g].x;
            As[(ac * 4 + 1) * PADA + m] = ra[g].y;
            As[(ac * 4 + 2) * PADA + m] = ra[g].z;
            As[(ac * 4 + 3) * PADA + m] = ra[g].w;
        }
#pragma unroll
        for (int g = 0; g < 2; ++g) {
            const int cc = bc + g * 4;
            Bs[(cc * 4 + 0) * PADB + br] = rb[g].x;
            Bs[(cc * 4 + 1) * PADB + br] = rb[g].y;
            Bs[(cc * 4 + 2) * PADB + br] = rb[g].z;
            Bs[(cc * 4 + 3) * PADB + br] = rb[g].w;
        }
    }
    __syncthreads();

    for (int kt = 0; kt < D / BK; ++kt) {
        const int s = kt & 1;
        const float* Ac = As + s * ASTRIDE;
        const float* Bc = Bs + s * BSTRIDE;

        if (kt < D / BK - 1) {
            const int k0 = (kt + 1) * BK;
#pragma unroll
            for (int g = 0; g < 4; ++g)
                ra[g] = *(const float4*)&X[(size_t)(Mb + ar + g * 32) * D + k0 + ac * 4];
#pragma unroll
            for (int g = 0; g < 2; ++g)
                rb[g] = *(const float4*)&Win[(size_t)(Nb + br) * D + k0 + (bc + g * 4) * 4];
        }

#pragma unroll
        for (int kk = 0; kk < BK; ++kk) {
            const float* asr = &Ac[kk * PADA + m0];
            unsigned long long a0 = *(const unsigned long long*)(asr + 0);
            unsigned long long a1 = *(const unsigned long long*)(asr + 2);
            unsigned long long a2 = *(const unsigned long long*)(asr + 4);
            unsigned long long a3 = *(const unsigned long long*)(asr + 6);
            float4 bv = *(const float4*)&Bc[kk * PADB + n0];
            unsigned long long b0 = pack_dup(bv.x);
            unsigned long long b1 = pack_dup(bv.y);
            unsigned long long b2 = pack_dup(bv.z);
            unsigned long long b3 = pack_dup(bv.w);
            fma2(acc[0][0], a0, b0); fma2(acc[0][1], a0, b1); fma2(acc[0][2], a0, b2); fma2(acc[0][3], a0, b3);
            fma2(acc[1][0], a1, b0); fma2(acc[1][1], a1, b1); fma2(acc[1][2], a1, b2); fma2(acc[1][3], a1, b3);
            fma2(acc[2][0], a2, b0); fma2(acc[2][1], a2, b1); fma2(acc[2][2], a2, b2); fma2(acc[2][3], a2, b3);
            fma2(acc[3][0], a3, b0); fma2(acc[3][1], a3, b1); fma2(acc[3][2], a3, b2); fma2(acc[3][3], a3, b3);
        }

        if (kt < D / BK - 1) {
            float* An = As + (s ^ 1) * ASTRIDE;
            float* Bn = Bs + (s ^ 1) * BSTRIDE;
#pragma unroll
            for (int g = 0; g < 4; ++g) {
                const int m = ar + g * 32;
                An[(ac * 4 + 0) * PADA + m] = ra[g].x;
                An[(ac * 4 + 1) * PADA + m] = ra[g].y;
                An[(ac * 4 + 2) * PADA + m] = ra[g].z;
                An[(ac * 4 + 3) * PADA + m] = ra[g].w;
            }
#pragma unroll
            for (int g = 0; g < 2; ++g) {
                const int cc = bc + g * 4;
                Bn[(cc * 4 + 0) * PADB + br] = rb[g].x;
                Bn[(cc * 4 + 1) * PADB + br] = rb[g].y;
                Bn[(cc * 4 + 2) * PADB + br] = rb[g].z;
                Bn[(cc * 4 + 3) * PADB + br] = rb[g].w;
            }
        }
        __syncthreads();
    }

    // store to g_ext with [t][b][o] layout: m = b*512 + t
#pragma unroll
    for (int i = 0; i < 4; ++i) {
        float lo[4], hi[4];
#pragma unroll
        for (int j = 0; j < 4; ++j) unpack2(acc[i][j], lo[j], hi[j]);
        const int m = Mb + m0 + 2 * i;
        const int b0i = m >> 9, t0i = m & 511;
        const int b1i = (m + 1) >> 9, t1i = (m + 1) & 511;
        *(float4*)&g_ext[((size_t)t0i * BATCH + b0i) * D + Nb + n0] = make_float4(lo[0], lo[1], lo[2], lo[3]);
        *(float4*)&g_ext[((size_t)t1i * BATCH + b1i) * D + Nb + n0] = make_float4(hi[0], hi[1], hi[2], hi[3]);
    }
}

// ---------------- Phase B: persistent recurrence, W_rec in registers ----------------
// Grid (32 n-tiles, 4 m-groups) = 128 CTAs, 512 threads, 1 CTA/SM.
// Warp w owns k-slice [w*64, w*64+64); lane l owns n = Nb+l; W fragment (64
// floats) lives in 32 f32x2 registers for the whole kernel. Per step:
//   - barrier wait (per-m-group, 32 CTAs)
//   - add-pass: s-tile (prefetched ext) += state (per-warp slice, syncwarp only)
//   - compute: 256 broadcast LDS.128 + 512 FFMA2 per warp -> acc[16 m]
//   - fold + smem reduction over 16 k-slices, ReLU, write state slice
//   - prefetch ext[t+1] into s-tile (overlaps next barrier)
#define NTILE 32
#define MTILE 16
#define SSTR  1028                       // floats per s-tile row (16B aligned, bank-skewed)
#define RED_OFF (MTILE * SSTR)           // red buffer after s-tile
#define PERS_SMEM ((MTILE * SSTR + 16 * 512) * 4)   // 98560 B

__global__ __launch_bounds__(512, 1) void rnn_persistent(const float* __restrict__ Wr) {
    extern __shared__ float sm[];
    float* sTile = sm;                   // [16][SSTR]
    float* red   = sm + RED_OFF;         // [16 kgroups][16 m * 32 n]

    const int tid = threadIdx.x;
    const int w   = tid >> 5;            // warp = k-slice
    const int l   = tid & 31;            // lane = n
    const int Nb  = blockIdx.x * NTILE;
    const int Mb  = blockIdx.y * MTILE;
    unsigned* bar = &g_bars[blockIdx.y * 32];

    // staging mapping: lane covers row r, half ch (8 float4 = 32 floats)
    const int r  = l & 15;
    const int ch = l >> 4;
    const int colf = w * 64 + ch * 32;   // element column base

    // ---- W fragment -> registers (held for all 512 steps) ----
    unsigned long long w2[32];
    {
        const float* wp = Wr + (size_t)(Nb + l) * D + w * 64;
#pragma unroll
        for (int j = 0; j < 16; ++j) {
            ulonglong2 v = *(const ulonglong2*)(wp + 4 * j);
            w2[2 * j] = v.x;
            w2[2 * j + 1] = v.y;
        }
    }

    // ---- preload ext[0] into s-tile (state0 == 0, so s = ext[0]) ----
    {
        const float* esrc = g_ext + (size_t)(Mb + r) * D + colf;   // t=0 block
        float* sdst = sTile + r * SSTR + colf;
#pragma unroll
        for (int j = 0; j < 8; ++j)
            *(float4*)(sdst + j * 4) = __ldg((const float4*)(esrc + j * 4));
    }
    __syncthreads();

    for (int t = 0; t < TLEN; ++t) {
        const float* sin = (t & 1) ? g_stateB : g_stateA;
        float* sout      = (t & 1) ? g_stateA : g_stateB;

        if (t > 0) {
            // ---- barrier: all CTAs in m-group finished step t-1 ----
            if (tid == 0) {
                const unsigned target = 32u * (unsigned)t;
                unsigned v;
                do {
                    asm volatile("ld.acquire.gpu.u32 %0, [%1];" : "=r"(v) : "l"(bar));
                } while (v < target);
            }
            __syncthreads();

            // ---- add state into prefetched ext tile (per-warp-private slice) ----
            const float* ssrc = sin + (size_t)(Mb + r) * D + colf;
            float* sdst = sTile + r * SSTR + colf;
#pragma unroll
            for (int j = 0; j < 8; j += 2) {
                float4 a0 = __ldcg((const float4*)(ssrc + j * 4));
                float4 a1 = __ldcg((const float4*)(ssrc + j * 4 + 4));
                float4 b0 = *(const float4*)(sdst + j * 4);
                float4 b1 = *(const float4*)(sdst + j * 4 + 4);
                *(float4*)(sdst + j * 4)     = make_float4(a0.x + b0.x, a0.y + b0.y, a0.z + b0.z, a0.w + b0.w);
                *(float4*)(sdst + j * 4 + 4) = make_float4(a1.x + b1.x, a1.y + b1.y, a1.z + b1.z, a1.w + b1.w);
            }
        }
        __syncwarp();

        // ---- compute: acc[m] over this warp's 64-k slice (broadcast LDS) ----
        unsigned long long acc[16];
#pragma unroll
        for (int i = 0; i < 16; ++i) acc[i] = 0ULL;

        const float* sb = sTile + w * 64;
#pragma unroll
        for (int m = 0; m < 16; ++m) {
            const ulonglong2* srow = (const ulonglong2*)(sb + m * SSTR);
#pragma unroll
            for (int j = 0; j < 16; ++j) {
                ulonglong2 sv = srow[j];
                fma2(acc[m], sv.x, w2[2 * j]);
                fma2(acc[m], sv.y, w2[2 * j + 1]);
            }
        }

        // ---- fold k-parity, write partials ----
#pragma unroll
        for (int m = 0; m < 16; ++m) {
            float lo, hi;
            unpack2(acc[m], lo, hi);
            red[w * 512 + m * 32 + l] = lo + hi;
        }
        __syncthreads();

        // ---- reduce over 16 k-slices, ReLU, write state slice ----
        {
            const int rm = tid >> 5, rn = tid & 31;
            float s0 = 0.f, s1 = 0.f;
#pragma unroll
            for (int g = 0; g < 16; g += 2) {
                s0 += red[g * 512 + rm * 32 + rn];
                s1 += red[(g + 1) * 512 + rm * 32 + rn];
            }
            const float v = fmaxf(s0 + s1, 0.f);
            __stcg(&sout[(size_t)(Mb + rm) * D + Nb + rn], v);
        }
        __syncthreads();   // all state writes done (also fences sTile reuse)

        // ---- arrive, then prefetch ext[t+1] (overlaps next barrier wait) ----
        if (tid == 0) {
            __threadfence();
            atomicAdd(bar, 1u);
        }
        if (t + 1 < TLEN) {
            const float* esrc = g_ext + (size_t)(t + 1) * (BATCH * D) + (size_t)(Mb + r) * D + colf;
            float* sdst = sTile + r * SSTR + colf;
#pragma unroll
            for (int j = 0; j < 8; j += 2) {
                float4 e0 = __ldg((const float4*)(esrc + j * 4));
                float4 e1 = __ldg((const float4*)(esrc + j * 4 + 4));
                *(float4*)(sdst + j * 4)     = e0;
                *(float4*)(sdst + j * 4 + 4) = e1;
            }
        }
    }
}

// ---------------- final: out[:,0,:] = final state ----------------
__global__ void final_copy_kernel(float* __restrict__ out) {
    const int i = blockIdx.x * blockDim.x + threadIdx.x;   // < 65536
    const int b = i >> 10, o = i & 1023;
    out[(size_t)b * (TLEN * D) + o] = g_stateA[i];
}

// ---------------- launch ----------------
extern "C" void kernel_launch(void* const* d_in, const int* in_sizes, int n_in,
                              void* d_out, int out_size) {
    const float* x     = (const float*)d_in[0];
    const float* W_in  = (const float*)d_in[1];
    const float* W_rec = (const float*)d_in[2];
    float* out = (float*)d_out;

    cudaFuncSetAttribute(rnn_persistent, cudaFuncAttributeMaxDynamicSharedMemorySize, PERS_SMEM);
    cudaFuncSetAttribute(ext_gemm_kernel, cudaFuncAttributeMaxDynamicSharedMemorySize, EXT_SMEM);

    // zero output (poisoned by harness), initial state, barrier counters
    zero4_kernel<<<(BATCH * TLEN * D / 4 + 255) / 256, 256>>>((float4*)out, BATCH * TLEN * D / 4);
    zero_state_kernel<<<(BATCH * D + 255) / 256, 256>>>();

    // Phase A: input projections for all timesteps (ext layout [t][b][o])
    ext_gemm_kernel<<<dim3(D / BN, (BATCH * TLEN) / BM), 256, EXT_SMEM>>>(x, W_in);

    // Phase B: full recurrence in one persistent kernel
    rnn_persistent<<<dim3(D / NTILE, BATCH / MTILE), 512, PERS_SMEM>>>(W_rec);

    // write final state into out[:,0,:]
    final_copy_kernel<<<(BATCH * D) / 256, 256>>>(out);
}

// round 6
// speedup vs baseline: 1.0129x; 1.0129x over previous
#include <cuda_runtime.h>
#include <cstdint>

#define BATCH 64
#define TLEN  512
#define D     1024

// ---------------- scratch (device globals: no allocations allowed) ----------------
__device__ float g_ext[(size_t)TLEN * BATCH * D];   // 128 MB, layout [t][b][o]
__device__ float g_stateA[BATCH * D];
__device__ float g_stateB[BATCH * D];
__device__ unsigned g_bars[4 * 32];                  // per-m-group barrier counters

// ---------------- packed f32x2 helpers (sm_103a FFMA2 path) ----------------
static __device__ __forceinline__ unsigned long long pack_dup(float w) {
    unsigned long long r;
    asm("mov.b64 %0, {%1, %1};" : "=l"(r) : "f"(w));
    return r;
}
static __device__ __forceinline__ void fma2(unsigned long long& d,
                                            unsigned long long a,
                                            unsigned long long b) {
    asm("fma.rn.f32x2 %0, %1, %2, %0;" : "+l"(d) : "l"(a), "l"(b));
}
static __device__ __forceinline__ void unpack2(unsigned long long v, float& lo, float& hi) {
    asm("mov.b64 {%0, %1}, %2;" : "=f"(lo), "=f"(hi) : "l"(v));
}

// ---------------- trivial zero kernels ----------------
__global__ void zero4_kernel(float4* __restrict__ p, int n4) {
    int i = blockIdx.x * blockDim.x + threadIdx.x;
    if (i < n4) p[i] = make_float4(0.f, 0.f, 0.f, 0.f);
}
__global__ void zero_state_kernel() {
    int i = blockIdx.x * blockDim.x + threadIdx.x;
    if (i < BATCH * D) g_stateA[i] = 0.f;
    if (i < 4 * 32) g_bars[i] = 0u;
}

// ---------------- Phase A: ext[t][b][o] = sum_k x[b][t][k] * W_in[o][k] ----------------
#define BM 128
#define BN 64
#define BK 32
#define PADA 134
#define PADB 68
#define ASTRIDE (BK * PADA)
#define BSTRIDE (BK * PADB)
#define EXT_SMEM ((2 * ASTRIDE + 2 * BSTRIDE) * 4)   // 51712 B

__global__ __launch_bounds__(256) void ext_gemm_kernel(const float* __restrict__ X,
                                                       const float* __restrict__ Win) {
    extern __shared__ float esm[];
    float* As = esm;
    float* Bs = esm + 2 * ASTRIDE;

    const int tid = threadIdx.x;
    const int Mb = blockIdx.y * BM;
    const int Nb = blockIdx.x * BN;
    const int ty = tid >> 4, tx = tid & 15;
    const int m0 = ty * 8, n0 = tx * 4;

    unsigned long long acc[4][4];
#pragma unroll
    for (int i = 0; i < 4; ++i)
#pragma unroll
        for (int j = 0; j < 4; ++j) acc[i][j] = 0ULL;

    const int ar = tid >> 3, ac = tid & 7;
    const int br = tid >> 2, bc = tid & 3;

    float4 ra[4], rb[2];
#pragma unroll
    for (int g = 0; g < 4; ++g)
        ra[g] = *(const float4*)&X[(size_t)(Mb + ar + g * 32) * D + ac * 4];
#pragma unroll
    for (int g = 0; g < 2; ++g)
        rb[g] = *(const float4*)&Win[(size_t)(Nb + br) * D + (bc + g * 4) * 4];
    {
#pragma unroll
        for (int g = 0; g < 4; ++g) {
            const int m = ar + g * 32;
            As[(ac * 4 + 0) * PADA + m] = ra[g].x;
            As[(ac * 4 + 1) * PADA + m] = ra[g].y;
            As[(ac * 4 + 2) * PADA + m] = ra[g].z;
            As[(ac * 4 + 3) * PADA + m] = ra[g].w;
        }
#pragma unroll
        for (int g = 0; g < 2; ++g) {
            const int cc = bc + g * 4;
            Bs[(cc * 4 + 0) * PADB + br] = rb[g].x;
            Bs[(cc * 4 + 1) * PADB + br] = rb[g].y;
            Bs[(cc * 4 + 2) * PADB + br] = rb[g].z;
            Bs[(cc * 4 + 3) * PADB + br] = rb[g].w;
        }
    }
    __syncthreads();

    for (int kt = 0; kt < D / BK; ++kt) {
        const int s = kt & 1;
        const float* Ac = As + s * ASTRIDE;
        const float* Bc = Bs + s * BSTRIDE;

        if (kt < D / BK - 1) {
            const int k0 = (kt + 1) * BK;
#pragma unroll
            for (int g = 0; g < 4; ++g)
                ra[g] = *(const float4*)&X[(size_t)(Mb + ar + g * 32) * D + k0 + ac * 4];
#pragma unroll
            for (int g = 0; g < 2; ++g)
                rb[g] = *(const float4*)&Win[(size_t)(Nb + br) * D + k0 + (bc + g * 4) * 4];
        }

#pragma unroll
        for (int kk = 0; kk < BK; ++kk) {
            const float* asr = &Ac[kk * PADA + m0];
            unsigned long long a0 = *(const unsigned long long*)(asr + 0);
            unsigned long long a1 = *(const unsigned long long*)(asr + 2);
            unsigned long long a2 = *(const unsigned long long*)(asr + 4);
            unsigned long long a3 = *(const unsigned long long*)(asr + 6);
            float4 bv = *(const float4*)&Bc[kk * PADB + n0];
            unsigned long long b0 = pack_dup(bv.x);
            unsigned long long b1 = pack_dup(bv.y);
            unsigned long long b2 = pack_dup(bv.z);
            unsigned long long b3 = pack_dup(bv.w);
            fma2(acc[0][0], a0, b0); fma2(acc[0][1], a0, b1); fma2(acc[0][2], a0, b2); fma2(acc[0][3], a0, b3);
            fma2(acc[1][0], a1, b0); fma2(acc[1][1], a1, b1); fma2(acc[1][2], a1, b2); fma2(acc[1][3], a1, b3);
            fma2(acc[2][0], a2, b0); fma2(acc[2][1], a2, b1); fma2(acc[2][2], a2, b2); fma2(acc[2][3], a2, b3);
            fma2(acc[3][0], a3, b0); fma2(acc[3][1], a3, b1); fma2(acc[3][2], a3, b2); fma2(acc[3][3], a3, b3);
        }

        if (kt < D / BK - 1) {
            float* An = As + (s ^ 1) * ASTRIDE;
            float* Bn = Bs + (s ^ 1) * BSTRIDE;
#pragma unroll
            for (int g = 0; g < 4; ++g) {
                const int m = ar + g * 32;
                An[(ac * 4 + 0) * PADA + m] = ra[g].x;
                An[(ac * 4 + 1) * PADA + m] = ra[g].y;
                An[(ac * 4 + 2) * PADA + m] = ra[g].z;
                An[(ac * 4 + 3) * PADA + m] = ra[g].w;
            }
#pragma unroll
            for (int g = 0; g < 2; ++g) {
                const int cc = bc + g * 4;
                Bn[(cc * 4 + 0) * PADB + br] = rb[g].x;
                Bn[(cc * 4 + 1) * PADB + br] = rb[g].y;
                Bn[(cc * 4 + 2) * PADB + br] = rb[g].z;
                Bn[(cc * 4 + 3) * PADB + br] = rb[g].w;
            }
        }
        __syncthreads();
    }

    // store to g_ext with [t][b][o] layout: m = b*512 + t
#pragma unroll
    for (int i = 0; i < 4; ++i) {
        float lo[4], hi[4];
#pragma unroll
        for (int j = 0; j < 4; ++j) unpack2(acc[i][j], lo[j], hi[j]);
        const int m = Mb + m0 + 2 * i;
        const int b0i = m >> 9, t0i = m & 511;
        const int b1i = (m + 1) >> 9, t1i = (m + 1) & 511;
        *(float4*)&g_ext[((size_t)t0i * BATCH + b0i) * D + Nb + n0] = make_float4(lo[0], lo[1], lo[2], lo[3]);
        *(float4*)&g_ext[((size_t)t1i * BATCH + b1i) * D + Nb + n0] = make_float4(hi[0], hi[1], hi[2], hi[3]);
    }
}

// ---------------- Phase B: persistent recurrence, W_rec in registers ----------------
// Grid (32 n-tiles, 4 m-groups) = 128 CTAs, 512 threads, 1 CTA/SM.
// Warp w owns k-slice [w*64, w*64+64); lane l owns n = Nb+l; W fragment =
// 32 f32x2 regs resident for all steps. Compute split into TWO m-passes of 8
// rows (acc[8] = 16 regs) so total live regs ~110 < 128 -> no spills.
// All compute-phase LDS are warp-uniform broadcasts (1 crossbar phase).
#define NTILE 32
#define MTILE 16
#define SSTR  1028
#define RED_OFF (MTILE * SSTR)
#define PERS_SMEM ((MTILE * SSTR + 16 * 512) * 4)   // 98560 B

__global__ __launch_bounds__(512, 1) void rnn_persistent(const float* __restrict__ Wr) {
    extern __shared__ float sm[];
    float* sTile = sm;                   // [16][SSTR]
    float* red   = sm + RED_OFF;         // [16 kgroups][16 m * 32 n]

    const int tid = threadIdx.x;
    const int w   = tid >> 5;            // warp = k-slice
    const int l   = tid & 31;            // lane = n
    const int Nb  = blockIdx.x * NTILE;
    const int Mb  = blockIdx.y * MTILE;
    unsigned* bar = &g_bars[blockIdx.y * 32];

    // staging mapping: lane covers row r, half ch (8 float4 = 32 floats)
    const int r  = l & 15;
    const int ch = l >> 4;
    const int colf = w * 64 + ch * 32;

    // ---- W fragment -> registers (held for all 512 steps) ----
    unsigned long long w2[32];
    {
        const float* wp = Wr + (size_t)(Nb + l) * D + w * 64;
#pragma unroll
        for (int j = 0; j < 16; ++j) {
            ulonglong2 v = *(const ulonglong2*)(wp + 4 * j);
            w2[2 * j] = v.x;
            w2[2 * j + 1] = v.y;
        }
    }

    // ---- preload ext[0] into s-tile (state0 == 0, so s = ext[0]) ----
    {
        const float* esrc = g_ext + (size_t)(Mb + r) * D + colf;   // t=0 block
        float* sdst = sTile + r * SSTR + colf;
#pragma unroll
        for (int j = 0; j < 8; ++j)
            *(float4*)(sdst + j * 4) = __ldg((const float4*)(esrc + j * 4));
    }
    __syncthreads();

    for (int t = 0; t < TLEN; ++t) {
        const float* sin = (t & 1) ? g_stateB : g_stateA;
        float* sout      = (t & 1) ? g_stateA : g_stateB;

        if (t > 0) {
            // ---- barrier: all CTAs in m-group finished step t-1 ----
            if (tid == 0) {
                const unsigned target = 32u * (unsigned)t;
                unsigned v;
                do {
                    asm volatile("ld.acquire.gpu.u32 %0, [%1];" : "=r"(v) : "l"(bar));
                } while (v < target);
            }
            __syncthreads();

            // ---- add state into prefetched ext tile (warp-private slice) ----
            const float* ssrc = sin + (size_t)(Mb + r) * D + colf;
            float* sdst = sTile + r * SSTR + colf;
#pragma unroll
            for (int j = 0; j < 8; j += 2) {
                float4 a0 = __ldcg((const float4*)(ssrc + j * 4));
                float4 a1 = __ldcg((const float4*)(ssrc + j * 4 + 4));
                float4 b0 = *(const float4*)(sdst + j * 4);
                float4 b1 = *(const float4*)(sdst + j * 4 + 4);
                *(float4*)(sdst + j * 4)     = make_float4(a0.x + b0.x, a0.y + b0.y, a0.z + b0.z, a0.w + b0.w);
                *(float4*)(sdst + j * 4 + 4) = make_float4(a1.x + b1.x, a1.y + b1.y, a1.z + b1.z, a1.w + b1.w);
            }
        }
        __syncwarp();

        // ---- compute in TWO m-passes of 8 rows (acc fits registers) ----
        const float* sb = sTile + w * 64;
#pragma unroll
        for (int pass = 0; pass < 2; ++pass) {
            unsigned long long acc[8];
#pragma unroll
            for (int i = 0; i < 8; ++i) acc[i] = 0ULL;

#pragma unroll
            for (int m = 0; m < 8; ++m) {
                const ulonglong2* srow = (const ulonglong2*)(sb + (size_t)(pass * 8 + m) * SSTR);
#pragma unroll
                for (int j = 0; j < 16; ++j) {
                    ulonglong2 sv = srow[j];
                    fma2(acc[m], sv.x, w2[2 * j]);
                    fma2(acc[m], sv.y, w2[2 * j + 1]);
                }
            }

#pragma unroll
            for (int m = 0; m < 8; ++m) {
                float lo, hi;
                unpack2(acc[m], lo, hi);
                red[w * 512 + (pass * 8 + m) * 32 + l] = lo + hi;
            }
        }
        __syncthreads();

        // ---- reduce over 16 k-slices, ReLU, write state slice ----
        {
            const int rm = tid >> 5, rn = tid & 31;
            float s0 = 0.f, s1 = 0.f;
#pragma unroll
            for (int g = 0; g < 16; g += 2) {
                s0 += red[g * 512 + rm * 32 + rn];
                s1 += red[(g + 1) * 512 + rm * 32 + rn];
            }
            const float v = fmaxf(s0 + s1, 0.f);
            __stcg(&sout[(size_t)(Mb + rm) * D + Nb + rn], v);
        }
        __syncthreads();   // all state writes done before arrive; sTile safe to overwrite

        // ---- arrive, then prefetch ext[t+1] (overlaps next barrier wait) ----
        if (tid == 0) {
            __threadfence();
            atomicAdd(bar, 1u);
        }
        if (t + 1 < TLEN) {
            const float* esrc = g_ext + (size_t)(t + 1) * (BATCH * D) + (size_t)(Mb + r) * D + colf;
            float* sdst = sTile + r * SSTR + colf;
#pragma unroll
            for (int j = 0; j < 8; j += 2) {
                float4 e0 = __ldg((const float4*)(esrc + j * 4));
                float4 e1 = __ldg((const float4*)(esrc + j * 4 + 4));
                *(float4*)(sdst + j * 4)     = e0;
                *(float4*)(sdst + j * 4 + 4) = e1;
            }
        }
    }
}

// ---------------- final: out[:,0,:] = final state ----------------
__global__ void final_copy_kernel(float* __restrict__ out) {
    const int i = blockIdx.x * blockDim.x + threadIdx.x;   // < 65536
    const int b = i >> 10, o = i & 1023;
    out[(size_t)b * (TLEN * D) + o] = g_stateA[i];
}

// ---------------- launch ----------------
extern "C" void kernel_launch(void* const* d_in, const int* in_sizes, int n_in,
                              void* d_out, int out_size) {
    const float* x     = (const float*)d_in[0];
    const float* W_in  = (const float*)d_in[1];
    const float* W_rec = (const float*)d_in[2];
    float* out = (float*)d_out;

    cudaFuncSetAttribute(rnn_persistent, cudaFuncAttributeMaxDynamicSharedMemorySize, PERS_SMEM);
    cudaFuncSetAttribute(ext_gemm_kernel, cudaFuncAttributeMaxDynamicSharedMemorySize, EXT_SMEM);

    // zero output (poisoned by harness), initial state, barrier counters
    zero4_kernel<<<(BATCH * TLEN * D / 4 + 255) / 256, 256>>>((float4*)out, BATCH * TLEN * D / 4);
    zero_state_kernel<<<(BATCH * D + 255) / 256, 256>>>();

    // Phase A: input projections for all timesteps (ext layout [t][b][o])
    ext_gemm_kernel<<<dim3(D / BN, (BATCH * TLEN) / BM), 256, EXT_SMEM>>>(x, W_in);

    // Phase B: full recurrence in one persistent kernel
    rnn_persistent<<<dim3(D / NTILE, BATCH / MTILE), 512, PERS_SMEM>>>(W_rec);

    // write final state into out[:,0,:]
    final_copy_kernel<<<(BATCH * D) / 256, 256>>>(out);
}

// round 7
// speedup vs baseline: 1.4209x; 1.4028x over previous
#include <cuda_runtime.h>
#include <cstdint>

#define BATCH 64
#define TLEN  512
#define D     1024

// ---------------- scratch (device globals: no allocations allowed) ----------------
__device__ float g_ext[(size_t)TLEN * BATCH * D];   // 128 MB, layout [t][b][o]
__device__ float g_stateA[BATCH * D];
__device__ float g_stateB[BATCH * D];
__device__ unsigned g_bars[4 * 32];                  // per-m-group barrier counters

// ---------------- packed f32x2 helpers (sm_103a FFMA2 path) ----------------
static __device__ __forceinline__ unsigned long long pack_dup(float w) {
    unsigned long long r;
    asm("mov.b64 %0, {%1, %1};" : "=l"(r) : "f"(w));
    return r;
}
static __device__ __forceinline__ void fma2(unsigned long long& d,
                                            unsigned long long a,
                                            unsigned long long b) {
    asm("fma.rn.f32x2 %0, %1, %2, %0;" : "+l"(d) : "l"(a), "l"(b));
}
static __device__ __forceinline__ void unpack2(unsigned long long v, float& lo, float& hi) {
    asm("mov.b64 {%0, %1}, %2;" : "=f"(lo), "=f"(hi) : "l"(v));
}

// ---------------- trivial zero kernels ----------------
__global__ void zero4_kernel(float4* __restrict__ p, int n4) {
    int i = blockIdx.x * blockDim.x + threadIdx.x;
    if (i < n4) p[i] = make_float4(0.f, 0.f, 0.f, 0.f);
}
__global__ void zero_state_kernel() {
    int i = blockIdx.x * blockDim.x + threadIdx.x;
    if (i < BATCH * D) g_stateA[i] = 0.f;
    if (i < 4 * 32) g_bars[i] = 0u;
}

// ---------------- Phase A: ext[t][b][o] = sum_k x[b][t][k] * W_in[o][k] ----------------
// BM=128, BN=64, BK=32, 256 threads, 8m x 4n per thread, double-buffered.
// launch_bounds(256,2): 2 CTAs/SM (4 warps/SMSP) to hide LDS latency and syncs.
#define BM 128
#define BN 64
#define BK 32
#define PADA 134
#define PADB 68
#define ASTRIDE (BK * PADA)
#define BSTRIDE (BK * PADB)
#define EXT_SMEM ((2 * ASTRIDE + 2 * BSTRIDE) * 4)   // 51712 B

__global__ __launch_bounds__(256, 2) void ext_gemm_kernel(const float* __restrict__ X,
                                                          const float* __restrict__ Win) {
    extern __shared__ float esm[];
    float* As = esm;
    float* Bs = esm + 2 * ASTRIDE;

    const int tid = threadIdx.x;
    const int Mb = blockIdx.y * BM;
    const int Nb = blockIdx.x * BN;
    const int ty = tid >> 4, tx = tid & 15;
    const int m0 = ty * 8, n0 = tx * 4;

    unsigned long long acc[4][4];
#pragma unroll
    for (int i = 0; i < 4; ++i)
#pragma unroll
        for (int j = 0; j < 4; ++j) acc[i][j] = 0ULL;

    const int ar = tid >> 3, ac = tid & 7;
    const int br = tid >> 2, bc = tid & 3;

    float4 ra[4], rb[2];
#pragma unroll
    for (int g = 0; g < 4; ++g)
        ra[g] = *(const float4*)&X[(size_t)(Mb + ar + g * 32) * D + ac * 4];
#pragma unroll
    for (int g = 0; g < 2; ++g)
        rb[g] = *(const float4*)&Win[(size_t)(Nb + br) * D + (bc + g * 4) * 4];
    {
#pragma unroll
        for (int g = 0; g < 4; ++g) {
            const int m = ar + g * 32;
            As[(ac * 4 + 0) * PADA + m] = ra[g].x;
            As[(ac * 4 + 1) * PADA + m] = ra[g].y;
            As[(ac * 4 + 2) * PADA + m] = ra[g].z;
            As[(ac * 4 + 3) * PADA + m] = ra[g].w;
        }
#pragma unroll
        for (int g = 0; g < 2; ++g) {
            const int cc = bc + g * 4;
            Bs[(cc * 4 + 0) * PADB + br] = rb[g].x;
            Bs[(cc * 4 + 1) * PADB + br] = rb[g].y;
            Bs[(cc * 4 + 2) * PADB + br] = rb[g].z;
            Bs[(cc * 4 + 3) * PADB + br] = rb[g].w;
        }
    }
    __syncthreads();

    for (int kt = 0; kt < D / BK; ++kt) {
        const int s = kt & 1;
        const float* Ac = As + s * ASTRIDE;
        const float* Bc = Bs + s * BSTRIDE;

        if (kt < D / BK - 1) {
            const int k0 = (kt + 1) * BK;
#pragma unroll
            for (int g = 0; g < 4; ++g)
                ra[g] = *(const float4*)&X[(size_t)(Mb + ar + g * 32) * D + k0 + ac * 4];
#pragma unroll
            for (int g = 0; g < 2; ++g)
                rb[g] = *(const float4*)&Win[(size_t)(Nb + br) * D + k0 + (bc + g * 4) * 4];
        }

#pragma unroll
        for (int kk = 0; kk < BK; ++kk) {
            const float* asr = &Ac[kk * PADA + m0];
            unsigned long long a0 = *(const unsigned long long*)(asr + 0);
            unsigned long long a1 = *(const unsigned long long*)(asr + 2);
            unsigned long long a2 = *(const unsigned long long*)(asr + 4);
            unsigned long long a3 = *(const unsigned long long*)(asr + 6);
            float4 bv = *(const float4*)&Bc[kk * PADB + n0];
            unsigned long long b0 = pack_dup(bv.x);
            unsigned long long b1 = pack_dup(bv.y);
            unsigned long long b2 = pack_dup(bv.z);
            unsigned long long b3 = pack_dup(bv.w);
            fma2(acc[0][0], a0, b0); fma2(acc[0][1], a0, b1); fma2(acc[0][2], a0, b2); fma2(acc[0][3], a0, b3);
            fma2(acc[1][0], a1, b0); fma2(acc[1][1], a1, b1); fma2(acc[1][2], a1, b2); fma2(acc[1][3], a1, b3);
            fma2(acc[2][0], a2, b0); fma2(acc[2][1], a2, b1); fma2(acc[2][2], a2, b2); fma2(acc[2][3], a2, b3);
            fma2(acc[3][0], a3, b0); fma2(acc[3][1], a3, b1); fma2(acc[3][2], a3, b2); fma2(acc[3][3], a3, b3);
        }

        if (kt < D / BK - 1) {
            float* An = As + (s ^ 1) * ASTRIDE;
            float* Bn = Bs + (s ^ 1) * BSTRIDE;
#pragma unroll
            for (int g = 0; g < 4; ++g) {
                const int m = ar + g * 32;
                An[(ac * 4 + 0) * PADA + m] = ra[g].x;
                An[(ac * 4 + 1) * PADA + m] = ra[g].y;
                An[(ac * 4 + 2) * PADA + m] = ra[g].z;
                An[(ac * 4 + 3) * PADA + m] = ra[g].w;
            }
#pragma unroll
            for (int g = 0; g < 2; ++g) {
                const int cc = bc + g * 4;
                Bn[(cc * 4 + 0) * PADB + br] = rb[g].x;
                Bn[(cc * 4 + 1) * PADB + br] = rb[g].y;
                Bn[(cc * 4 + 2) * PADB + br] = rb[g].z;
                Bn[(cc * 4 + 3) * PADB + br] = rb[g].w;
            }
        }
        __syncthreads();
    }

    // store to g_ext with [t][b][o] layout: m = b*512 + t
#pragma unroll
    for (int i = 0; i < 4; ++i) {
        float lo[4], hi[4];
#pragma unroll
        for (int j = 0; j < 4; ++j) unpack2(acc[i][j], lo[j], hi[j]);
        const int m = Mb + m0 + 2 * i;
        const int b0i = m >> 9, t0i = m & 511;
        const int b1i = (m + 1) >> 9, t1i = (m + 1) & 511;
        *(float4*)&g_ext[((size_t)t0i * BATCH + b0i) * D + Nb + n0] = make_float4(lo[0], lo[1], lo[2], lo[3]);
        *(float4*)&g_ext[((size_t)t1i * BATCH + b1i) * D + Nb + n0] = make_float4(hi[0], hi[1], hi[2], hi[3]);
    }
}

// ---------------- Phase B: persistent recurrence, W_rec in registers ----------------
// 256 threads (8 warps), launch_bounds(256,1) -> 255-reg budget, NO spills:
// W frag = 128 floats (64 f32x2 regs), acc[16] = 32 regs, ~200 total.
// Warp w owns k-slice [w*128, w*128+128); lane l owns column n = Nb+l.
// All compute-phase LDS are warp-uniform 16B broadcasts (1 crossbar phase).
#define NTILE 32
#define MTILE 16
#define SSTR  1028
#define PERS_SMEM ((MTILE * SSTR + 8 * 512) * 4)   // 82176 B

__global__ __launch_bounds__(256, 1) void rnn_persistent(const float* __restrict__ Wr) {
    extern __shared__ float sm[];
    float* sTile = sm;                   // [16][SSTR]
    float* red   = sm + MTILE * SSTR;    // [8 kgroups][16 m * 32 n]

    const int tid = threadIdx.x;
    const int w   = tid >> 5;            // warp = 128-wide k-slice (0..7)
    const int l   = tid & 31;            // lane = n
    const int Nb  = blockIdx.x * NTILE;
    const int Mb  = blockIdx.y * MTILE;
    unsigned* bar = &g_bars[blockIdx.y * 32];

    // staging mapping: row r (16 rows), 16 threads per row, 16 float4 each
    const int r  = tid >> 4;             // 0..15
    const int c0 = tid & 15;             // float4 column base

    // ---- W fragment -> registers (128 floats, held for all 512 steps) ----
    unsigned long long w2[64];
    {
        const float* wp = Wr + (size_t)(Nb + l) * D + w * 128;
#pragma unroll
        for (int j = 0; j < 32; ++j) {
            ulonglong2 v = *(const ulonglong2*)(wp + 4 * j);
            w2[2 * j]     = v.x;
            w2[2 * j + 1] = v.y;
        }
    }

    // ---- preload ext[0] into s-tile (state0 == 0, so s = ext[0]) ----
    {
        const float4* esrc = (const float4*)(g_ext + (size_t)(Mb + r) * D);
        float* sdst = sTile + r * SSTR;
#pragma unroll
        for (int j = 0; j < 16; ++j) {
            const int q = c0 + j * 16;
            *(float4*)(sdst + q * 4) = __ldg(esrc + q);
        }
    }
    __syncthreads();

    for (int t = 0; t < TLEN; ++t) {
        float* sout = (t & 1) ? g_stateA : g_stateB;

        if (t > 0) {
            const float* sin = (t & 1) ? g_stateB : g_stateA;
            // ---- barrier: all CTAs in m-group finished step t-1 ----
            if (tid == 0) {
                const unsigned target = 32u * (unsigned)t;
                unsigned v;
                do {
                    asm volatile("ld.acquire.gpu.u32 %0, [%1];" : "=r"(v) : "l"(bar));
                } while (v < target);
            }
            __syncthreads();

            // ---- add state into prefetched ext tile ----
            const float4* ssrc = (const float4*)(sin + (size_t)(Mb + r) * D);
            float* sdst = sTile + r * SSTR;
#pragma unroll
            for (int j = 0; j < 16; j += 2) {
                const int q0 = c0 + j * 16;
                const int q1 = c0 + (j + 1) * 16;
                float4 a0 = __ldcg(ssrc + q0);
                float4 a1 = __ldcg(ssrc + q1);
                float4 b0 = *(const float4*)(sdst + q0 * 4);
                float4 b1 = *(const float4*)(sdst + q1 * 4);
                *(float4*)(sdst + q0 * 4) = make_float4(a0.x + b0.x, a0.y + b0.y, a0.z + b0.z, a0.w + b0.w);
                *(float4*)(sdst + q1 * 4) = make_float4(a1.x + b1.x, a1.y + b1.y, a1.z + b1.z, a1.w + b1.w);
            }
            __syncthreads();   // all rows staged before any warp computes
        }

        // ---- compute: acc[16 m] over this warp's 128-k slice (broadcast LDS) ----
        unsigned long long acc[16];
#pragma unroll
        for (int i = 0; i < 16; ++i) acc[i] = 0ULL;

        const float* sb = sTile + w * 128;
#pragma unroll
        for (int m = 0; m < 16; ++m) {
            const ulonglong2* srow = (const ulonglong2*)(sb + (size_t)m * SSTR);
#pragma unroll
            for (int j = 0; j < 32; ++j) {
                ulonglong2 sv = srow[j];
                fma2(acc[m], sv.x, w2[2 * j]);
                fma2(acc[m], sv.y, w2[2 * j + 1]);
            }
        }

        // ---- fold k-parity, write partials (conflict-free) ----
#pragma unroll
        for (int m = 0; m < 16; ++m) {
            float lo, hi;
            unpack2(acc[m], lo, hi);
            red[w * 512 + m * 32 + l] = lo + hi;
        }
        __syncthreads();

        // ---- reduce over 8 k-slices, ReLU, write state (2 outputs/thread) ----
#pragma unroll
        for (int rep = 0; rep < 2; ++rep) {
            const int idx = tid + rep * 256;
            const int rm = idx >> 5, rn = idx & 31;
            float s0 = 0.f, s1 = 0.f;
#pragma unroll
            for (int g = 0; g < 8; g += 2) {
                s0 += red[g * 512 + idx];
                s1 += red[(g + 1) * 512 + idx];
            }
            __stcg(&sout[(size_t)(Mb + rm) * D + Nb + rn], fmaxf(s0 + s1, 0.f));
        }
        __syncthreads();   // all state writes done before arrive; sTile safe to overwrite

        // ---- arrive, then prefetch ext[t+1] (overlaps other CTAs' compute) ----
        if (tid == 0) {
            __threadfence();
            atomicAdd(bar, 1u);
        }
        if (t + 1 < TLEN) {
            const float4* esrc = (const float4*)(g_ext + (size_t)(t + 1) * (BATCH * D) + (size_t)(Mb + r) * D);
            float* sdst = sTile + r * SSTR;
#pragma unroll
            for (int j = 0; j < 16; ++j) {
                const int q = c0 + j * 16;
                *(float4*)(sdst + q * 4) = __ldg(esrc + q);
            }
        }
    }
}

// ---------------- final: out[:,0,:] = final state ----------------
__global__ void final_copy_kernel(float* __restrict__ out) {
    const int i = blockIdx.x * blockDim.x + threadIdx.x;   // < 65536
    const int b = i >> 10, o = i & 1023;
    out[(size_t)b * (TLEN * D) + o] = g_stateA[i];
}

// ---------------- launch ----------------
extern "C" void kernel_launch(void* const* d_in, const int* in_sizes, int n_in,
                              void* d_out, int out_size) {
    const float* x     = (const float*)d_in[0];
    const float* W_in  = (const float*)d_in[1];
    const float* W_rec = (const float*)d_in[2];
    float* out = (float*)d_out;

    cudaFuncSetAttribute(rnn_persistent, cudaFuncAttributeMaxDynamicSharedMemorySize, PERS_SMEM);
    cudaFuncSetAttribute(ext_gemm_kernel, cudaFuncAttributeMaxDynamicSharedMemorySize, EXT_SMEM);

    // zero output (poisoned by harness), initial state, barrier counters
    zero4_kernel<<<(BATCH * TLEN * D / 4 + 255) / 256, 256>>>((float4*)out, BATCH * TLEN * D / 4);
    zero_state_kernel<<<(BATCH * D + 255) / 256, 256>>>();

    // Phase A: input projections for all timesteps (ext layout [t][b][o])
    ext_gemm_kernel<<<dim3(D / BN, (BATCH * TLEN) / BM), 256, EXT_SMEM>>>(x, W_in);

    // Phase B: full recurrence in one persistent kernel
    rnn_persistent<<<dim3(D / NTILE, BATCH / MTILE), 256, PERS_SMEM>>>(W_rec);

    // write final state into out[:,0,:]
    final_copy_kernel<<<(BATCH * D) / 256, 256>>>(out);
}